// round 14
// baseline (speedup 1.0000x reference)
#include <cuda_runtime.h>
#include <cstdint>

#define BB 4
#define NN 65536
#define QQ 400
#define CC 20
#define MM 64
#define CH 1024                  // rows per sort chunk
#define NCHUNK (NN / CH)         // 64 chunks per batch
#define TQ 4                     // q-tile for kfin (400 = 100*4)

// ---------------- device scratch (no mallocs allowed) ----------------
__device__ float g_accX[BB*MM*QQ];     // sum x per (b,m,q)
__device__ float g_accG[BB*MM*QQ];     // sum sigmoid per (b,m,q)
__device__ float g_accL[BB*QQ];        // sum log2(sigma(-x)) per (b,q)  [negative]
__device__ int   g_segmax[BB*MM];      // inst_seg
__device__ int   g_mstart[BB*MM];      // per-batch start offset of each m
__device__ int   g_hist[BB*MM*NCHUNK]; // [b][m][chunk] counts
__device__ int   g_smaxc[BB*MM*NCHUNK];// [b][m][chunk] per-chunk seg max
__device__ unsigned short g_rank[BB*NN];   // packed (m<<10)|rank_within_chunk
__device__ unsigned short g_sorder[BB*NN]; // point indices grouped by m

// ---------------- fast approx ops ----------------
__device__ __forceinline__ float tanha(float x){ float r; asm("tanh.approx.f32 %0, %1;" : "=f"(r) : "f"(x)); return r; }
__device__ __forceinline__ float lg2a(float x){ float r; asm("lg2.approx.f32 %0, %1;" : "=f"(r) : "f"(x)); return r; }
__device__ __forceinline__ float rcpa(float x){ float r; asm("rcp.approx.f32 %0, %1;" : "=f"(r) : "f"(x)); return r; }

// ---------------- pass 1: histogram + rank recording + segmax + zero accs ----
__global__ void __launch_bounds__(256) khist(const int* __restrict__ inst,
                                             const int* __restrict__ seg) {
    const int b   = blockIdx.y;
    const int ch  = blockIdx.x;
    const int tid = threadIdx.x;
    __shared__ int h[MM];
    __shared__ int smax[MM];
    if (tid < MM) { h[tid] = 0; smax[tid] = 0; }
    __syncthreads();

    // fused zeroing of accumulators (256 blocks x 256 thr, 2 strides)
    const int gtid = (b * NCHUNK + ch) * 256 + tid;            // 0..65535
    #pragma unroll
    for (int j = gtid; j < BB*MM*QQ; j += BB*NCHUNK*256) {
        g_accX[j] = 0.f;
        g_accG[j] = 0.f;
    }
    if (gtid < BB*QQ) g_accL[gtid] = 0.f;

    // vectorized histogram; atomicAdd return value = rank within (chunk, m)
    const int base = ch * CH;                     // 1024 elems; 256 thr x int4
    const int n0 = base + tid * 4;
    int4 mi = __ldg(reinterpret_cast<const int4*>(inst + b * NN + n0));
    int4 si = __ldg(reinterpret_cast<const int4*>(seg  + b * NN + n0));
    ushort4 rk;
    {
        int r0 = atomicAdd(&h[mi.x], 1); atomicMax(&smax[mi.x], si.x);
        int r1 = atomicAdd(&h[mi.y], 1); atomicMax(&smax[mi.y], si.y);
        int r2 = atomicAdd(&h[mi.z], 1); atomicMax(&smax[mi.z], si.z);
        int r3 = atomicAdd(&h[mi.w], 1); atomicMax(&smax[mi.w], si.w);
        rk.x = (unsigned short)((mi.x << 10) | r0);
        rk.y = (unsigned short)((mi.y << 10) | r1);
        rk.z = (unsigned short)((mi.z << 10) | r2);
        rk.w = (unsigned short)((mi.w << 10) | r3);
    }
    *reinterpret_cast<ushort4*>(g_rank + b * NN + n0) = rk;
    __syncthreads();
    if (tid < MM) {
        g_hist [(b * MM + tid) * NCHUNK + ch] = h[tid];
        g_smaxc[(b * MM + tid) * NCHUNK + ch] = smax[tid];
    }
}

// ---------------- pass 2: per-block in-shared scan + atomic-free scatter -----
__global__ void __launch_bounds__(256) kscatter() {
    const int b   = blockIdx.y;
    const int ch  = blockIdx.x;
    const int tid = threadIdx.x;

    // load the full per-batch histogram (64 m x 64 ch = 4096 ints, 16 KB)
    __shared__ int sh[MM * NCHUNK];
    #pragma unroll
    for (int j = tid; j < MM * NCHUNK; j += 256)
        sh[j] = g_hist[b * MM * NCHUNK + j];
    __syncthreads();

    __shared__ int rowtot[MM];
    __shared__ int partial[MM];
    if (tid < MM) {
        const int m = tid;
        int pre = 0, tot = 0;
        #pragma unroll 8
        for (int c = 0; c < NCHUNK; c++) {
            int v = sh[m * NCHUNK + c];
            pre += (c < ch) ? v : 0;
            tot += v;
        }
        rowtot[m]  = tot;
        partial[m] = pre;
    }
    __syncthreads();

    __shared__ int off[MM];
    if (tid < MM) {
        int base = 0;                      // exclusive scan over m (64 bcast reads)
        for (int m2 = 0; m2 < tid; m2++) base += rowtot[m2];
        off[tid] = base + partial[tid];
        if (ch == 0) {
            g_mstart[b * MM + tid] = base;
            const int* sc = g_smaxc + (b * MM + tid) * NCHUNK;
            int mx = 0;
            #pragma unroll 8
            for (int c = 0; c < NCHUNK; c++) mx = max(mx, sc[c]);
            g_segmax[b * MM + tid] = mx;
        }
    }
    __syncthreads();

    // atomic-free scatter using recorded ranks (vectorized rank read)
    const int base = ch * CH;
    const int n0 = base + tid * 4;
    ushort4 rk = *reinterpret_cast<const ushort4*>(g_rank + b * NN + n0);
    unsigned short* so = g_sorder + b * NN;
    so[off[rk.x >> 10] + (rk.x & 1023)] = (unsigned short)(n0);
    so[off[rk.y >> 10] + (rk.y & 1023)] = (unsigned short)(n0 + 1);
    so[off[rk.z >> 10] + (rk.z & 1023)] = (unsigned short)(n0 + 2);
    so[off[rk.w >> 10] + (rk.w & 1023)] = (unsigned short)(n0 + 3);
}

// ---------------- main accumulation kernel (frozen R6 shape) ----------------
// th = tanh(x/2): sigma(x)-0.5 = th/2; sigma(-x) = 0.5 - 0.5*th
// softplus(x) = -ln(sigma(-x))  -> batched product of sigma(-x) + one lg2
#define ELEM_BODY(VX, SX, SG, PP) {              \
    float x_  = (VX);                            \
    float th_ = tanha(0.5f * x_);                \
    (SG) += 0.5f * th_;                          \
    (SX) += x_;                                  \
    (PP) *= fmaf(-0.5f, th_, 0.5f); }

__global__ void __launch_bounds__(128, 7) kmain(const float* __restrict__ mask) {
    const int b    = blockIdx.z;
    const int lane = threadIdx.x & 31;
    const int w    = threadIdx.x >> 5;
    const int wc   = blockIdx.x * 4 + w;            // 0..147
    const int RPW  = (NN + 147) / 148;              // 443 rows per warp
    int i  = wc * RPW;
    const int r1 = min(i + RPW, NN);

    const int qb = blockIdx.y * 64;
    const int q0 = qb + 2 * lane;
    const bool valid = (q0 < QQ);
    const int qc = valid ? q0 : qb;                 // clamp into a touched sector

    // mstart table in warp registers
    const int* ms = g_mstart + b * MM;
    const int ms0 = ms[lane];
    const int ms1 = ms[lane + 32];

    unsigned bal0 = __ballot_sync(0xffffffffu, ms0 <= i);
    unsigned bal1 = __ballot_sync(0xffffffffu, ms1 <= i);
    int m = __popc(bal0) + __popc(bal1) - 1;        // last m with start <= i

    auto seg_end = [&](int mm) -> int {
        int nm = mm + 1;
        int lo = __shfl_sync(0xffffffffu, ms0, nm & 31);
        int hi = __shfl_sync(0xffffffffu, ms1, nm & 31);
        return (nm >= MM) ? NN : ((nm < 32) ? lo : hi);
    };

    const unsigned short* __restrict__ so = g_sorder + b * NN;
    const float* __restrict__ xb = mask + (size_t)b * NN * QQ + qc;

    float L0 = 0.f, L1 = 0.f;

    while (i < r1) {
        while (seg_end(m) <= i) ++m;
        const int e   = min(r1, seg_end(m));
        const int s0i = i;
        float sx0 = 0.f, sx1 = 0.f, sg0 = 0.f, sg1 = 0.f;
        float p0 = 1.f, p1 = 1.f;

        // unroll-8: front-batched indices, 8 streaming gathers in flight
        for (; i + 8 <= e; i += 8) {
            int ns[8];
            #pragma unroll
            for (int k = 0; k < 8; k++) ns[k] = so[i + k];
            float2 v[8];
            #pragma unroll
            for (int k = 0; k < 8; k++)
                v[k] = __ldcs(reinterpret_cast<const float2*>(xb + (size_t)ns[k] * QQ));
            #pragma unroll
            for (int k = 0; k < 8; k++) {
                ELEM_BODY(v[k].x, sx0, sg0, p0);
                ELEM_BODY(v[k].y, sx1, sg1, p1);
            }
            L0 += lg2a(p0); p0 = 1.f;
            L1 += lg2a(p1); p1 = 1.f;
        }
        for (; i < e; ++i) {
            int ns = so[i];
            float2 v = __ldcs(reinterpret_cast<const float2*>(xb + (size_t)ns * QQ));
            ELEM_BODY(v.x, sx0, sg0, p0);
            ELEM_BODY(v.y, sx1, sg1, p1);
        }
        L0 += lg2a(p0);
        L1 += lg2a(p1);

        // flush per-m sums (warp-uniform m; 256B coalesced atomic region)
        const int scnt = e - s0i;
        if (valid & (scnt > 0)) {
            float half = 0.5f * (float)scnt;
            float* aX = g_accX + ((b * MM + m) * QQ);
            float* aG = g_accG + ((b * MM + m) * QQ);
            atomicAdd(aX + q0,     sx0);
            atomicAdd(aX + q0 + 1, sx1);
            atomicAdd(aG + q0,     sg0 + half);
            atomicAdd(aG + q0 + 1, sg1 + half);
        }
    }
    if (valid) {
        atomicAdd(g_accL + b * QQ + q0,     L0);
        atomicAdd(g_accL + b * QQ + q0 + 1, L1);
    }
}

// ---------------- finalize: 400-block latency-optimized combine -------------
__global__ void __launch_bounds__(256) kfin(const float* __restrict__ cls,
                                            float* __restrict__ out) {
    const int qt  = blockIdx.x;          // 0..99 (4 q each)
    const int b   = blockIdx.y;
    const int tid = threadIdx.x;
    const int ql  = tid & (TQ - 1);      // q within tile
    const int m   = tid >> 2;            // 0..63
    const int qbase = qt * TQ;
    const int q = qbase + ql;

    __shared__ float s_prob[TQ][CC];
    __shared__ float s_SP[TQ];
    __shared__ float tP[TQ * 65];
    __shared__ float tG[TQ * 65];
    __shared__ float s_part[16][TQ];
    __shared__ float s_sig[TQ];
    __shared__ int   s_seg[MM];
    __shared__ float s_cnt[MM];

    // one load wave: everything issued before the first barrier
    const float X = g_accX[(b * MM + m) * QQ + q];
    const float G = g_accG[(b * MM + m) * QQ + q];

    if (tid < MM) {
        s_seg[tid] = g_segmax[b * MM + tid];
        int st = g_mstart[b * MM + tid];
        int en = (tid < MM - 1) ? g_mstart[b * MM + tid + 1] : NN;
        s_cnt[tid] = (float)(en - st);
    } else if (tid < MM + TQ) {          // per-q softmax (4 threads)
        const int j = tid - MM;
        const float* cl = cls + ((size_t)b * QQ + qbase + j) * CC;
        float v[CC];
        float mx = -1e30f;
        #pragma unroll
        for (int c = 0; c < CC; c++) { v[c] = __ldg(cl + c); mx = fmaxf(mx, v[c]); }
        float sum = 0.f;
        #pragma unroll
        for (int c = 0; c < CC; c++) { float e = __expf(v[c] - mx); s_prob[j][c] = e; sum += e; }
        float inv = rcpa(sum);
        #pragma unroll
        for (int c = 0; c < CC; c++) s_prob[j][c] *= inv;
    } else if (tid < MM + 2 * TQ) {
        const int j = tid - MM - TQ;
        s_SP[j] = -0.6931471805599453f * g_accL[b * QQ + qbase + j];
    }
    __syncthreads();

    const float invN = 1.0f / (float)NN;
    tP[ql * 65 + m] = (s_SP[ql] - X) * invN + 1.0f - s_prob[ql][s_seg[m]] + 1.0f;
    tG[ql * 65 + m] = G;
    __syncthreads();

    if (tid < 64) {                      // stage 1: 16 groups x 4 m
        const int qq = tid & 3, grp = tid >> 2;
        float s = 0.f;
        #pragma unroll
        for (int j2 = 0; j2 < 4; j2++) s += tG[qq * 65 + grp * 4 + j2];
        s_part[grp][qq] = s;
    }
    __syncthreads();
    if (tid < TQ) {                      // stage 2: 16 partials
        float s = 0.f;
        #pragma unroll
        for (int j2 = 0; j2 < 16; j2++) s += s_part[j2][tid];
        s_sig[tid] = s;
    }
    __syncthreads();

    // coalesced contiguous write: 4 q x 64 m = 256 floats, one per thread
    {
        const int qloc = tid >> 6, mm = tid & 63;
        float Gv = tG[qloc * 65 + mm];
        out[((size_t)b * QQ + qbase) * MM + tid] =
            tP[qloc * 65 + mm] - (2.0f * Gv + 1.0f) * rcpa(s_sig[qloc] + s_cnt[mm] + 1.0f);
    }
}

// ---------------- launcher ----------------
extern "C" void kernel_launch(void* const* d_in, const int* in_sizes, int n_in,
                              void* d_out, int out_size) {
    const float* mask = (const float*)d_in[0];   // [B,N,Q]
    const float* cls  = (const float*)d_in[1];   // [B,Q,C]
    const int*   inst = (const int*)d_in[2];     // [B,N]
    const int*   seg  = (const int*)d_in[3];     // [B,N]
    float*       out  = (float*)d_out;           // [B,Q,M]

    khist<<<dim3(NCHUNK, BB), 256>>>(inst, seg);
    kscatter<<<dim3(NCHUNK, BB), 256>>>();
    kmain<<<dim3(37, 7, BB), 128>>>(mask);
    kfin<<<dim3(QQ / TQ, BB), 256>>>(cls, out);
}

// round 16
// speedup vs baseline: 1.0067x; 1.0067x over previous
#include <cuda_runtime.h>
#include <cstdint>

#define BB 4
#define NN 65536
#define QQ 400
#define CC 20
#define MM 64
#define CH 1024                  // rows per sort chunk
#define NCHUNK (NN / CH)         // 64 chunks per batch
#define TQ 4                     // q-tile for kfin (400 = 100*4)

#define NCOMBO 28                // 4 batches x 7 q-tiles
#define WPC 169                  // warp-chunks per combo
#define RPW 388                  // ceil(NN / WPC)
#define NWARP (NCOMBO * WPC)     // 4732 warps
#define NBLKM ((NWARP + 3) / 4)  // 1183 blocks -> 7.99/SM, single wave @8/SM

// ---------------- device scratch (no mallocs allowed) ----------------
__device__ float g_accX[BB*MM*QQ];     // sum x per (b,m,q)
__device__ float g_accG[BB*MM*QQ];     // sum sigmoid per (b,m,q)
__device__ float g_accL[BB*QQ];        // sum log2(sigma(-x)) per (b,q)  [negative]
__device__ int   g_segmax[BB*MM];      // inst_seg
__device__ int   g_mstart[BB*MM];      // per-batch start offset of each m
__device__ int   g_hist[BB*MM*NCHUNK]; // [b][m][chunk] counts
__device__ int   g_smaxc[BB*MM*NCHUNK];// [b][m][chunk] per-chunk seg max
__device__ unsigned short g_rank[BB*NN];   // packed (m<<10)|rank_within_chunk
__device__ unsigned short g_sorder[BB*NN]; // point indices grouped by m

// ---------------- fast approx ops ----------------
__device__ __forceinline__ float tanha(float x){ float r; asm("tanh.approx.f32 %0, %1;" : "=f"(r) : "f"(x)); return r; }
__device__ __forceinline__ float lg2a(float x){ float r; asm("lg2.approx.f32 %0, %1;" : "=f"(r) : "f"(x)); return r; }
__device__ __forceinline__ float rcpa(float x){ float r; asm("rcp.approx.f32 %0, %1;" : "=f"(r) : "f"(x)); return r; }

// ---------------- pass 1: histogram + rank recording + segmax + zero accs ----
__global__ void __launch_bounds__(256) khist(const int* __restrict__ inst,
                                             const int* __restrict__ seg) {
    const int b   = blockIdx.y;
    const int ch  = blockIdx.x;
    const int tid = threadIdx.x;
    __shared__ int h[MM];
    __shared__ int smax[MM];
    if (tid < MM) { h[tid] = 0; smax[tid] = 0; }
    __syncthreads();

    // fused zeroing of accumulators (256 blocks x 256 thr, 2 strides)
    const int gtid = (b * NCHUNK + ch) * 256 + tid;            // 0..65535
    #pragma unroll
    for (int j = gtid; j < BB*MM*QQ; j += BB*NCHUNK*256) {
        g_accX[j] = 0.f;
        g_accG[j] = 0.f;
    }
    if (gtid < BB*QQ) g_accL[gtid] = 0.f;

    // vectorized histogram; atomicAdd return value = rank within (chunk, m)
    const int base = ch * CH;                     // 1024 elems; 256 thr x int4
    const int n0 = base + tid * 4;
    int4 mi = __ldg(reinterpret_cast<const int4*>(inst + b * NN + n0));
    int4 si = __ldg(reinterpret_cast<const int4*>(seg  + b * NN + n0));
    ushort4 rk;
    {
        int r0 = atomicAdd(&h[mi.x], 1); atomicMax(&smax[mi.x], si.x);
        int r1 = atomicAdd(&h[mi.y], 1); atomicMax(&smax[mi.y], si.y);
        int r2 = atomicAdd(&h[mi.z], 1); atomicMax(&smax[mi.z], si.z);
        int r3 = atomicAdd(&h[mi.w], 1); atomicMax(&smax[mi.w], si.w);
        rk.x = (unsigned short)((mi.x << 10) | r0);
        rk.y = (unsigned short)((mi.y << 10) | r1);
        rk.z = (unsigned short)((mi.z << 10) | r2);
        rk.w = (unsigned short)((mi.w << 10) | r3);
    }
    *reinterpret_cast<ushort4*>(g_rank + b * NN + n0) = rk;
    __syncthreads();
    if (tid < MM) {
        g_hist [(b * MM + tid) * NCHUNK + ch] = h[tid];
        g_smaxc[(b * MM + tid) * NCHUNK + ch] = smax[tid];
    }
}

// ---------------- pass 2: per-block in-shared scan + atomic-free scatter -----
__global__ void __launch_bounds__(256) kscatter() {
    const int b   = blockIdx.y;
    const int ch  = blockIdx.x;
    const int tid = threadIdx.x;

    // load the full per-batch histogram (64 m x 64 ch = 4096 ints, 16 KB)
    __shared__ int sh[MM * NCHUNK];
    #pragma unroll
    for (int j = tid; j < MM * NCHUNK; j += 256)
        sh[j] = g_hist[b * MM * NCHUNK + j];
    __syncthreads();

    __shared__ int rowtot[MM];
    __shared__ int partial[MM];
    if (tid < MM) {
        const int m = tid;
        int pre = 0, tot = 0;
        #pragma unroll 8
        for (int c = 0; c < NCHUNK; c++) {
            int v = sh[m * NCHUNK + c];
            pre += (c < ch) ? v : 0;
            tot += v;
        }
        rowtot[m]  = tot;
        partial[m] = pre;
    }
    __syncthreads();

    __shared__ int off[MM];
    if (tid < MM) {
        int base = 0;                      // exclusive scan over m (64 bcast reads)
        for (int m2 = 0; m2 < tid; m2++) base += rowtot[m2];
        off[tid] = base + partial[tid];
        if (ch == 0) {
            g_mstart[b * MM + tid] = base;
            const int* sc = g_smaxc + (b * MM + tid) * NCHUNK;
            int mx = 0;
            #pragma unroll 8
            for (int c = 0; c < NCHUNK; c++) mx = max(mx, sc[c]);
            g_segmax[b * MM + tid] = mx;
        }
    }
    __syncthreads();

    // atomic-free scatter using recorded ranks (vectorized rank read)
    const int base = ch * CH;
    const int n0 = base + tid * 4;
    ushort4 rk = *reinterpret_cast<const ushort4*>(g_rank + b * NN + n0);
    unsigned short* so = g_sorder + b * NN;
    so[off[rk.x >> 10] + (rk.x & 1023)] = (unsigned short)(n0);
    so[off[rk.y >> 10] + (rk.y & 1023)] = (unsigned short)(n0 + 1);
    so[off[rk.z >> 10] + (rk.z & 1023)] = (unsigned short)(n0 + 2);
    so[off[rk.w >> 10] + (rk.w & 1023)] = (unsigned short)(n0 + 3);
}

// ---------------- main accumulation kernel ----------------
// th = tanh(x/2): sigma(x)-0.5 = th/2; sigma(-x) = 0.5 - 0.5*th
// softplus(x) = -ln(sigma(-x))  -> batched product of sigma(-x) + one lg2
#define ELEM_BODY(VX, SX, SG, PP) {              \
    float x_  = (VX);                            \
    float th_ = tanha(0.5f * x_);                \
    (SG) += 0.5f * th_;                          \
    (SX) += x_;                                  \
    (PP) *= fmaf(-0.5f, th_, 0.5f); }

__global__ void __launch_bounds__(128, 8) kmain(const float* __restrict__ mask) {
    // warp-flattened work: 4732 warps over 28 (b, q-tile) combos x 169 chunks.
    // 1183 blocks @ 8/SM = single wave, 32 warps/SM.
    const int lane = threadIdx.x & 31;
    const int w    = threadIdx.x >> 5;
    const int W    = blockIdx.x * 4 + w;            // 0..4731
    const int combo = W / WPC;                      // 0..27 (b*7 + y)
    const int chunk = W % WPC;                      // 0..168
    const int b    = combo / 7;
    const int y    = combo % 7;
    int i  = chunk * RPW;
    const int r1 = min(i + RPW, NN);

    const int qb = y * 64;
    const int q0 = qb + 2 * lane;
    const bool valid = (q0 < QQ);
    const int qc = valid ? q0 : qb;                 // clamp into a touched sector

    // mstart table in warp registers
    const int* ms = g_mstart + b * MM;
    const int ms0 = ms[lane];
    const int ms1 = ms[lane + 32];

    unsigned bal0 = __ballot_sync(0xffffffffu, ms0 <= i);
    unsigned bal1 = __ballot_sync(0xffffffffu, ms1 <= i);
    int m = __popc(bal0) + __popc(bal1) - 1;        // last m with start <= i

    auto seg_end = [&](int mm) -> int {
        int nm = mm + 1;
        int lo = __shfl_sync(0xffffffffu, ms0, nm & 31);
        int hi = __shfl_sync(0xffffffffu, ms1, nm & 31);
        return (nm >= MM) ? NN : ((nm < 32) ? lo : hi);
    };

    const unsigned short* __restrict__ so = g_sorder + b * NN;
    const float* __restrict__ xb = mask + (size_t)b * NN * QQ + qc;

    float L0 = 0.f, L1 = 0.f;

    while (i < r1) {
        while (seg_end(m) <= i) ++m;
        const int e   = min(r1, seg_end(m));
        const int s0i = i;
        float sx0 = 0.f, sx1 = 0.f, sg0 = 0.f, sg1 = 0.f;
        float p0 = 1.f, p1 = 1.f;

        // unroll-8: front-batched indices, 8 streaming gathers in flight
        for (; i + 8 <= e; i += 8) {
            int ns[8];
            #pragma unroll
            for (int k = 0; k < 8; k++) ns[k] = so[i + k];
            float2 v[8];
            #pragma unroll
            for (int k = 0; k < 8; k++)
                v[k] = __ldcs(reinterpret_cast<const float2*>(xb + (size_t)ns[k] * QQ));
            #pragma unroll
            for (int k = 0; k < 8; k++) {
                ELEM_BODY(v[k].x, sx0, sg0, p0);
                ELEM_BODY(v[k].y, sx1, sg1, p1);
            }
            L0 += lg2a(p0); p0 = 1.f;
            L1 += lg2a(p1); p1 = 1.f;
        }
        for (; i < e; ++i) {
            int ns = so[i];
            float2 v = __ldcs(reinterpret_cast<const float2*>(xb + (size_t)ns * QQ));
            ELEM_BODY(v.x, sx0, sg0, p0);
            ELEM_BODY(v.y, sx1, sg1, p1);
        }
        L0 += lg2a(p0);
        L1 += lg2a(p1);

        // flush per-m sums (warp-uniform m; 256B coalesced atomic region)
        const int scnt = e - s0i;
        if (valid & (scnt > 0)) {
            float half = 0.5f * (float)scnt;
            float* aX = g_accX + ((b * MM + m) * QQ);
            float* aG = g_accG + ((b * MM + m) * QQ);
            atomicAdd(aX + q0,     sx0);
            atomicAdd(aX + q0 + 1, sx1);
            atomicAdd(aG + q0,     sg0 + half);
            atomicAdd(aG + q0 + 1, sg1 + half);
        }
    }
    if (valid) {
        atomicAdd(g_accL + b * QQ + q0,     L0);
        atomicAdd(g_accL + b * QQ + q0 + 1, L1);
    }
}

// ---------------- finalize: 400-block latency-optimized combine -------------
__global__ void __launch_bounds__(256) kfin(const float* __restrict__ cls,
                                            float* __restrict__ out) {
    const int qt  = blockIdx.x;          // 0..99 (4 q each)
    const int b   = blockIdx.y;
    const int tid = threadIdx.x;
    const int ql  = tid & (TQ - 1);      // q within tile
    const int m   = tid >> 2;            // 0..63
    const int qbase = qt * TQ;
    const int q = qbase + ql;

    __shared__ float s_prob[TQ][CC];
    __shared__ float s_SP[TQ];
    __shared__ float tP[TQ * 65];
    __shared__ float tG[TQ * 65];
    __shared__ float s_part[16][TQ];
    __shared__ float s_sig[TQ];
    __shared__ int   s_seg[MM];
    __shared__ float s_cnt[MM];

    // one load wave: everything issued before the first barrier
    const float X = g_accX[(b * MM + m) * QQ + q];
    const float G = g_accG[(b * MM + m) * QQ + q];

    if (tid < MM) {
        s_seg[tid] = g_segmax[b * MM + tid];
        int st = g_mstart[b * MM + tid];
        int en = (tid < MM - 1) ? g_mstart[b * MM + tid + 1] : NN;
        s_cnt[tid] = (float)(en - st);
    } else if (tid < MM + TQ) {          // per-q softmax (4 threads)
        const int j = tid - MM;
        const float* cl = cls + ((size_t)b * QQ + qbase + j) * CC;
        float v[CC];
        float mx = -1e30f;
        #pragma unroll
        for (int c = 0; c < CC; c++) { v[c] = __ldg(cl + c); mx = fmaxf(mx, v[c]); }
        float sum = 0.f;
        #pragma unroll
        for (int c = 0; c < CC; c++) { float e = __expf(v[c] - mx); s_prob[j][c] = e; sum += e; }
        float inv = rcpa(sum);
        #pragma unroll
        for (int c = 0; c < CC; c++) s_prob[j][c] *= inv;
    } else if (tid < MM + 2 * TQ) {
        const int j = tid - MM - TQ;
        s_SP[j] = -0.6931471805599453f * g_accL[b * QQ + qbase + j];
    }
    __syncthreads();

    const float invN = 1.0f / (float)NN;
    tP[ql * 65 + m] = (s_SP[ql] - X) * invN + 1.0f - s_prob[ql][s_seg[m]] + 1.0f;
    tG[ql * 65 + m] = G;
    __syncthreads();

    if (tid < 64) {                      // stage 1: 16 groups x 4 m
        const int qq = tid & 3, grp = tid >> 2;
        float s = 0.f;
        #pragma unroll
        for (int j2 = 0; j2 < 4; j2++) s += tG[qq * 65 + grp * 4 + j2];
        s_part[grp][qq] = s;
    }
    __syncthreads();
    if (tid < TQ) {                      // stage 2: 16 partials
        float s = 0.f;
        #pragma unroll
        for (int j2 = 0; j2 < 16; j2++) s += s_part[j2][tid];
        s_sig[tid] = s;
    }
    __syncthreads();

    // coalesced contiguous write: 4 q x 64 m = 256 floats, one per thread
    {
        const int qloc = tid >> 6, mm = tid & 63;
        float Gv = tG[qloc * 65 + mm];
        out[((size_t)b * QQ + qbase) * MM + tid] =
            tP[qloc * 65 + mm] - (2.0f * Gv + 1.0f) * rcpa(s_sig[qloc] + s_cnt[mm] + 1.0f);
    }
}

// ---------------- launcher ----------------
extern "C" void kernel_launch(void* const* d_in, const int* in_sizes, int n_in,
                              void* d_out, int out_size) {
    const float* mask = (const float*)d_in[0];   // [B,N,Q]
    const float* cls  = (const float*)d_in[1];   // [B,Q,C]
    const int*   inst = (const int*)d_in[2];     // [B,N]
    const int*   seg  = (const int*)d_in[3];     // [B,N]
    float*       out  = (float*)d_out;           // [B,Q,M]

    khist<<<dim3(NCHUNK, BB), 256>>>(inst, seg);
    kscatter<<<dim3(NCHUNK, BB), 256>>>();
    kmain<<<NBLKM, 128>>>(mask);
    kfin<<<dim3(QQ / TQ, BB), 256>>>(cls, out);
}

// round 17
// speedup vs baseline: 1.0216x; 1.0148x over previous
#include <cuda_runtime.h>
#include <cstdint>

#define BB 4
#define NN 65536
#define QQ 400
#define CC 20
#define MM 64
#define CH 1024                  // rows per sort chunk
#define NCHUNK (NN / CH)         // 64 chunks per batch
#define TQ 4                     // q-tile for kfin (400 = 100*4)

// ---------------- device scratch (no mallocs allowed) ----------------
__device__ float g_accX[BB*MM*QQ];     // sum x per (b,m,q)
__device__ float g_accG[BB*MM*QQ];     // sum sigmoid per (b,m,q)
__device__ float g_accL[BB*QQ];        // sum log2(sigma(-x)) per (b,q)  [negative]
__device__ int   g_segmax[BB*MM];      // inst_seg
__device__ int   g_mstart[BB*MM];      // per-batch start offset of each m
__device__ int   g_hist[BB*MM*NCHUNK]; // [b][m][chunk] counts
__device__ int   g_smaxc[BB*MM*NCHUNK];// [b][m][chunk] per-chunk seg max
__device__ unsigned short g_rank[BB*NN];   // packed (m<<10)|rank_within_chunk
__device__ unsigned short g_sorder[BB*NN]; // point indices grouped by m

// ---------------- fast approx ops ----------------
__device__ __forceinline__ float tanha(float x){ float r; asm("tanh.approx.f32 %0, %1;" : "=f"(r) : "f"(x)); return r; }
__device__ __forceinline__ float lg2a(float x){ float r; asm("lg2.approx.f32 %0, %1;" : "=f"(r) : "f"(x)); return r; }
__device__ __forceinline__ float rcpa(float x){ float r; asm("rcp.approx.f32 %0, %1;" : "=f"(r) : "f"(x)); return r; }

// ---------------- pass 1: histogram + rank recording + segmax + zero accs ----
__global__ void __launch_bounds__(256) khist(const int* __restrict__ inst,
                                             const int* __restrict__ seg) {
    const int b   = blockIdx.y;
    const int ch  = blockIdx.x;
    const int tid = threadIdx.x;
    __shared__ int h[MM];
    __shared__ int smax[MM];
    if (tid < MM) { h[tid] = 0; smax[tid] = 0; }
    __syncthreads();

    // fused zeroing of accumulators (256 blocks x 256 thr, 2 strides)
    const int gtid = (b * NCHUNK + ch) * 256 + tid;            // 0..65535
    #pragma unroll
    for (int j = gtid; j < BB*MM*QQ; j += BB*NCHUNK*256) {
        g_accX[j] = 0.f;
        g_accG[j] = 0.f;
    }
    if (gtid < BB*QQ) g_accL[gtid] = 0.f;

    // vectorized histogram; atomicAdd return value = rank within (chunk, m)
    const int base = ch * CH;                     // 1024 elems; 256 thr x int4
    const int n0 = base + tid * 4;
    int4 mi = __ldg(reinterpret_cast<const int4*>(inst + b * NN + n0));
    int4 si = __ldg(reinterpret_cast<const int4*>(seg  + b * NN + n0));
    ushort4 rk;
    {
        int r0 = atomicAdd(&h[mi.x], 1); atomicMax(&smax[mi.x], si.x);
        int r1 = atomicAdd(&h[mi.y], 1); atomicMax(&smax[mi.y], si.y);
        int r2 = atomicAdd(&h[mi.z], 1); atomicMax(&smax[mi.z], si.z);
        int r3 = atomicAdd(&h[mi.w], 1); atomicMax(&smax[mi.w], si.w);
        rk.x = (unsigned short)((mi.x << 10) | r0);
        rk.y = (unsigned short)((mi.y << 10) | r1);
        rk.z = (unsigned short)((mi.z << 10) | r2);
        rk.w = (unsigned short)((mi.w << 10) | r3);
    }
    *reinterpret_cast<ushort4*>(g_rank + b * NN + n0) = rk;
    __syncthreads();
    if (tid < MM) {
        g_hist [(b * MM + tid) * NCHUNK + ch] = h[tid];
        g_smaxc[(b * MM + tid) * NCHUNK + ch] = smax[tid];
    }
}

// ---------------- pass 2: per-block in-shared scan + atomic-free scatter -----
__global__ void __launch_bounds__(256) kscatter() {
    const int b   = blockIdx.y;
    const int ch  = blockIdx.x;
    const int tid = threadIdx.x;

    // load the full per-batch histogram (64 m x 64 ch = 4096 ints, 16 KB)
    __shared__ int sh[MM * NCHUNK];
    #pragma unroll
    for (int j = tid; j < MM * NCHUNK; j += 256)
        sh[j] = g_hist[b * MM * NCHUNK + j];
    __syncthreads();

    __shared__ int rowtot[MM];
    __shared__ int partial[MM];
    if (tid < MM) {
        const int m = tid;
        int pre = 0, tot = 0;
        #pragma unroll 8
        for (int c = 0; c < NCHUNK; c++) {
            int v = sh[m * NCHUNK + c];
            pre += (c < ch) ? v : 0;
            tot += v;
        }
        rowtot[m]  = tot;
        partial[m] = pre;
    }
    __syncthreads();

    __shared__ int off[MM];
    if (tid < MM) {
        int base = 0;                      // exclusive scan over m (64 bcast reads)
        for (int m2 = 0; m2 < tid; m2++) base += rowtot[m2];
        off[tid] = base + partial[tid];
        if (ch == 0) {
            g_mstart[b * MM + tid] = base;
            const int* sc = g_smaxc + (b * MM + tid) * NCHUNK;
            int mx = 0;
            #pragma unroll 8
            for (int c = 0; c < NCHUNK; c++) mx = max(mx, sc[c]);
            g_segmax[b * MM + tid] = mx;
        }
    }
    __syncthreads();

    // atomic-free scatter using recorded ranks (vectorized rank read)
    const int base = ch * CH;
    const int n0 = base + tid * 4;
    ushort4 rk = *reinterpret_cast<const ushort4*>(g_rank + b * NN + n0);
    unsigned short* so = g_sorder + b * NN;
    so[off[rk.x >> 10] + (rk.x & 1023)] = (unsigned short)(n0);
    so[off[rk.y >> 10] + (rk.y & 1023)] = (unsigned short)(n0 + 1);
    so[off[rk.z >> 10] + (rk.z & 1023)] = (unsigned short)(n0 + 2);
    so[off[rk.w >> 10] + (rk.w & 1023)] = (unsigned short)(n0 + 3);
}

// ---------------- main accumulation kernel: row-co-scheduled q-tiles --------
// Block = 7 warps; warp w handles q-tile w over the SAME row range, so each
// 1600B mask row is consumed in full by one block nearly simultaneously
// (DRAM page locality + single L1-resident sorder stream).
// th = tanh(x/2): sigma(x)-0.5 = th/2; sigma(-x) = 0.5 - 0.5*th
// softplus(x) = -ln(sigma(-x))  -> batched product of sigma(-x) + one lg2
#define ELEM_BODY(VX, SX, SG, PP) {              \
    float x_  = (VX);                            \
    float th_ = tanha(0.5f * x_);                \
    (SG) += 0.5f * th_;                          \
    (SX) += x_;                                  \
    (PP) *= fmaf(-0.5f, th_, 0.5f); }

__global__ void __launch_bounds__(224, 4) kmain(const float* __restrict__ mask) {
    const int b    = blockIdx.y;
    const int lane = threadIdx.x & 31;
    const int y    = threadIdx.x >> 5;              // warp = q-tile 0..6
    const int RPW  = (NN + 147) / 148;              // 443 rows per block
    int i  = blockIdx.x * RPW;
    const int r1 = min(i + RPW, NN);

    const int qb = y * 64;
    const int q0 = qb + 2 * lane;
    const bool valid = (q0 < QQ);
    const int qc = valid ? q0 : qb;                 // clamp into a touched sector

    // mstart table in warp registers
    const int* ms = g_mstart + b * MM;
    const int ms0 = ms[lane];
    const int ms1 = ms[lane + 32];

    unsigned bal0 = __ballot_sync(0xffffffffu, ms0 <= i);
    unsigned bal1 = __ballot_sync(0xffffffffu, ms1 <= i);
    int m = __popc(bal0) + __popc(bal1) - 1;        // last m with start <= i

    auto seg_end = [&](int mm) -> int {
        int nm = mm + 1;
        int lo = __shfl_sync(0xffffffffu, ms0, nm & 31);
        int hi = __shfl_sync(0xffffffffu, ms1, nm & 31);
        return (nm >= MM) ? NN : ((nm < 32) ? lo : hi);
    };

    const unsigned short* __restrict__ so = g_sorder + b * NN;
    const float* __restrict__ xb = mask + (size_t)b * NN * QQ + qc;

    float L0 = 0.f, L1 = 0.f;

    while (i < r1) {
        while (seg_end(m) <= i) ++m;
        const int e   = min(r1, seg_end(m));
        const int s0i = i;
        float sx0 = 0.f, sx1 = 0.f, sg0 = 0.f, sg1 = 0.f;
        float p0 = 1.f, p1 = 1.f;

        // unroll-8: front-batched indices, 8 streaming gathers in flight
        for (; i + 8 <= e; i += 8) {
            int ns[8];
            #pragma unroll
            for (int k = 0; k < 8; k++) ns[k] = so[i + k];
            float2 v[8];
            #pragma unroll
            for (int k = 0; k < 8; k++)
                v[k] = __ldcs(reinterpret_cast<const float2*>(xb + (size_t)ns[k] * QQ));
            #pragma unroll
            for (int k = 0; k < 8; k++) {
                ELEM_BODY(v[k].x, sx0, sg0, p0);
                ELEM_BODY(v[k].y, sx1, sg1, p1);
            }
            L0 += lg2a(p0); p0 = 1.f;
            L1 += lg2a(p1); p1 = 1.f;
        }
        for (; i < e; ++i) {
            int ns = so[i];
            float2 v = __ldcs(reinterpret_cast<const float2*>(xb + (size_t)ns * QQ));
            ELEM_BODY(v.x, sx0, sg0, p0);
            ELEM_BODY(v.y, sx1, sg1, p1);
        }
        L0 += lg2a(p0);
        L1 += lg2a(p1);

        // flush per-m sums (warp-uniform m; 256B coalesced atomic region)
        const int scnt = e - s0i;
        if (valid & (scnt > 0)) {
            float half = 0.5f * (float)scnt;
            float* aX = g_accX + ((b * MM + m) * QQ);
            float* aG = g_accG + ((b * MM + m) * QQ);
            atomicAdd(aX + q0,     sx0);
            atomicAdd(aX + q0 + 1, sx1);
            atomicAdd(aG + q0,     sg0 + half);
            atomicAdd(aG + q0 + 1, sg1 + half);
        }
    }
    if (valid) {
        atomicAdd(g_accL + b * QQ + q0,     L0);
        atomicAdd(g_accL + b * QQ + q0 + 1, L1);
    }
}

// ---------------- finalize: 400-block latency-optimized combine -------------
__global__ void __launch_bounds__(256) kfin(const float* __restrict__ cls,
                                            float* __restrict__ out) {
    const int qt  = blockIdx.x;          // 0..99 (4 q each)
    const int b   = blockIdx.y;
    const int tid = threadIdx.x;
    const int ql  = tid & (TQ - 1);      // q within tile
    const int m   = tid >> 2;            // 0..63
    const int qbase = qt * TQ;
    const int q = qbase + ql;

    __shared__ float s_prob[TQ][CC];
    __shared__ float s_SP[TQ];
    __shared__ float tP[TQ * 65];
    __shared__ float tG[TQ * 65];
    __shared__ float s_part[16][TQ];
    __shared__ float s_sig[TQ];
    __shared__ int   s_seg[MM];
    __shared__ float s_cnt[MM];

    // one load wave: everything issued before the first barrier
    const float X = g_accX[(b * MM + m) * QQ + q];
    const float G = g_accG[(b * MM + m) * QQ + q];

    if (tid < MM) {
        s_seg[tid] = g_segmax[b * MM + tid];
        int st = g_mstart[b * MM + tid];
        int en = (tid < MM - 1) ? g_mstart[b * MM + tid + 1] : NN;
        s_cnt[tid] = (float)(en - st);
    } else if (tid < MM + TQ) {          // per-q softmax (4 threads)
        const int j = tid - MM;
        const float* cl = cls + ((size_t)b * QQ + qbase + j) * CC;
        float v[CC];
        float mx = -1e30f;
        #pragma unroll
        for (int c = 0; c < CC; c++) { v[c] = __ldg(cl + c); mx = fmaxf(mx, v[c]); }
        float sum = 0.f;
        #pragma unroll
        for (int c = 0; c < CC; c++) { float e = __expf(v[c] - mx); s_prob[j][c] = e; sum += e; }
        float inv = rcpa(sum);
        #pragma unroll
        for (int c = 0; c < CC; c++) s_prob[j][c] *= inv;
    } else if (tid < MM + 2 * TQ) {
        const int j = tid - MM - TQ;
        s_SP[j] = -0.6931471805599453f * g_accL[b * QQ + qbase + j];
    }
    __syncthreads();

    const float invN = 1.0f / (float)NN;
    tP[ql * 65 + m] = (s_SP[ql] - X) * invN + 1.0f - s_prob[ql][s_seg[m]] + 1.0f;
    tG[ql * 65 + m] = G;
    __syncthreads();

    if (tid < 64) {                      // stage 1: 16 groups x 4 m
        const int qq = tid & 3, grp = tid >> 2;
        float s = 0.f;
        #pragma unroll
        for (int j2 = 0; j2 < 4; j2++) s += tG[qq * 65 + grp * 4 + j2];
        s_part[grp][qq] = s;
    }
    __syncthreads();
    if (tid < TQ) {                      // stage 2: 16 partials
        float s = 0.f;
        #pragma unroll
        for (int j2 = 0; j2 < 16; j2++) s += s_part[j2][tid];
        s_sig[tid] = s;
    }
    __syncthreads();

    // coalesced contiguous write: 4 q x 64 m = 256 floats, one per thread
    {
        const int qloc = tid >> 6, mm = tid & 63;
        float Gv = tG[qloc * 65 + mm];
        out[((size_t)b * QQ + qbase) * MM + tid] =
            tP[qloc * 65 + mm] - (2.0f * Gv + 1.0f) * rcpa(s_sig[qloc] + s_cnt[mm] + 1.0f);
    }
}

// ---------------- launcher ----------------
extern "C" void kernel_launch(void* const* d_in, const int* in_sizes, int n_in,
                              void* d_out, int out_size) {
    const float* mask = (const float*)d_in[0];   // [B,N,Q]
    const float* cls  = (const float*)d_in[1];   // [B,Q,C]
    const int*   inst = (const int*)d_in[2];     // [B,N]
    const int*   seg  = (const int*)d_in[3];     // [B,N]
    float*       out  = (float*)d_out;           // [B,Q,M]

    khist<<<dim3(NCHUNK, BB), 256>>>(inst, seg);
    kscatter<<<dim3(NCHUNK, BB), 256>>>();
    kmain<<<dim3(148, BB), 224>>>(mask);
    kfin<<<dim3(QQ / TQ, BB), 256>>>(cls, out);
}